// round 8
// baseline (speedup 1.0000x reference)
#include <cuda_runtime.h>
#include <cuda_bf16.h>

// ---------------------------------------------------------------------------
// Problem constants
//   U=100000, I=20000, D=64, H=128, B=64
//   out = [likes (64x20000), sim (64x64), rated (64x20000), popular (20000)]
// ---------------------------------------------------------------------------
#define N_ITEMS 20000
#define DIM     64
#define HDIM    128
#define BATCH   64

// Scratch layout (floats) inside one __device__ global (no allocation allowed).
#define LI_LIKES 0
#define LI_RATED 2560000            // 20000*128
#define LI_POP   5120000
#define UB_OFF   7680000            // 2 heads * 64 * 128
#define ZUB_OFF  7696384            // 128 zeros (never written -> stays 0)
#define SCRATCH_FLOATS 7696512

__device__ float g_scratch[SCRATCH_FLOATS];   // zero-initialized at load

typedef unsigned long long u64;

__device__ __forceinline__ u64 dup2(float x) {
    u64 d; asm("mov.b64 %0,{%1,%1};" : "=l"(d) : "f"(x)); return d;
}
__device__ __forceinline__ u64 fma2(u64 a, u64 b, u64 c) {
    u64 d; asm("fma.rn.f32x2 %0,%1,%2,%3;" : "=l"(d) : "l"(a), "l"(b), "l"(c)); return d;
}
__device__ __forceinline__ void unpack2(u64 v, float& lo, float& hi) {
    asm("mov.b64 {%0,%1},%2;" : "=f"(lo), "=f"(hi) : "l"(v));
}

// ---------------------------------------------------------------------------
// user_kernel (1 block):
//   eu = user_embedding[users]                     (64 x 64)
//   ub[h][b][k] = eu@W0[:64] + b0   (likes, rated) -> g_scratch[UB_OFF..]
//   sim = -(n @ n^T), n = row-normalized eu        -> sim_out
// ---------------------------------------------------------------------------
__global__ void __launch_bounds__(256) user_kernel(
    const int* __restrict__ users, const float* __restrict__ UE,
    const float* __restrict__ lW0, const float* __restrict__ lb0,
    const float* __restrict__ rW0, const float* __restrict__ rb0,
    float* __restrict__ sim_out)
{
    __shared__ float eu[64][65];
    __shared__ float Ws[64][64];
    __shared__ float inv[64];
    int tid = threadIdx.x;

    for (int o = tid; o < 4096; o += 256) {
        int b = o >> 6, d = o & 63;
        eu[b][d] = UE[(size_t)users[b] * DIM + d];
    }
    __syncthreads();

    for (int h = 0; h < 2; h++) {
        const float* W0 = h ? rW0 : lW0;
        const float* b0 = h ? rb0 : lb0;
        for (int kh = 0; kh < 2; kh++) {
            // user half of W0: rows 0..63, cols kh*64..kh*64+63
            for (int o = tid; o < 4096; o += 256) {
                int d = o >> 6, kc = o & 63;
                Ws[d][kc] = W0[d * HDIM + kh * 64 + kc];
            }
            __syncthreads();
            int kc = tid & 63, bg = tid >> 6;
            int k = kh * 64 + kc;
            for (int b = bg; b < 64; b += 4) {
                float acc = b0[k];
                #pragma unroll
                for (int d = 0; d < 64; d++) acc += eu[b][d] * Ws[d][kc];
                g_scratch[UB_OFF + h * (BATCH * HDIM) + b * HDIM + k] = acc;
            }
            __syncthreads();
        }
    }

    if (tid < 64) {
        float ss = 0.f;
        #pragma unroll
        for (int d = 0; d < 64; d++) { float x = eu[tid][d]; ss += x * x; }
        inv[tid] = rsqrtf(fmaxf(ss, 1e-12f));
    }
    __syncthreads();
    for (int o = tid; o < 4096; o += 256) {
        int p = o >> 6, q = o & 63;
        float s = 0.f;
        #pragma unroll
        for (int d = 0; d < 64; d++) s += eu[p][d] * eu[q][d];
        sim_out[o] = -s * inv[p] * inv[q];
    }
}

// ---------------------------------------------------------------------------
// proj_kernel: O[i][n] = sum_d E[i][d]*W[d][n] (+bias[n])
//   E: [n_items][64], W: [64][128], O -> g_scratch + o_off, [n_items][128]
//   Tile 128x128, K=64 in chunks of 16. 256 threads, 8x8 per thread.
// ---------------------------------------------------------------------------
__global__ void __launch_bounds__(256) proj_kernel(
    const float* __restrict__ E, const float* __restrict__ W,
    const float* __restrict__ bias, int o_off, int n_items, int has_bias)
{
    float* O = g_scratch + o_off;
    __shared__ float Es[16][132];
    __shared__ float Ws[16][132];
    int tid = threadIdx.x, tx = tid & 15, ty = tid >> 4;
    int i0 = blockIdx.x * 128;

    float acc[8][8];
    #pragma unroll
    for (int m = 0; m < 8; m++)
        #pragma unroll
        for (int n = 0; n < 8; n++) acc[m][n] = 0.f;

    #pragma unroll 1
    for (int kk = 0; kk < 64; kk += 16) {
        #pragma unroll
        for (int r = 0; r < 2; r++) {
            int q = tid + r * 256;
            int row = q >> 5, c = (q & 31) << 2;
            *(float4*)&Ws[row][c] = *(const float4*)(W + (kk + row) * HDIM + c);
        }
        #pragma unroll
        for (int r = 0; r < 2; r++) {
            int q = tid + r * 256;
            int i = q >> 2, kq = (q & 3) << 2;
            float4 v = make_float4(0.f, 0.f, 0.f, 0.f);
            if (i0 + i < n_items) v = *(const float4*)(E + (i0 + i) * DIM + kk + kq);
            Es[kq + 0][i] = v.x; Es[kq + 1][i] = v.y;
            Es[kq + 2][i] = v.z; Es[kq + 3][i] = v.w;
        }
        __syncthreads();
        #pragma unroll
        for (int k = 0; k < 16; k++) {
            float a[8], bb[8];
            #pragma unroll
            for (int mi = 0; mi < 2; mi++)
                #pragma unroll
                for (int j = 0; j < 4; j++) a[mi * 4 + j] = Es[k][mi * 64 + ty * 4 + j];
            #pragma unroll
            for (int ni = 0; ni < 2; ni++)
                #pragma unroll
                for (int j = 0; j < 4; j++) bb[ni * 4 + j] = Ws[k][ni * 64 + tx * 4 + j];
            #pragma unroll
            for (int m = 0; m < 8; m++)
                #pragma unroll
                for (int n = 0; n < 8; n++) acc[m][n] += a[m] * bb[n];
        }
        __syncthreads();
    }

    #pragma unroll
    for (int m = 0; m < 8; m++) {
        int i = i0 + (m >> 2) * 64 + ty * 4 + (m & 3);
        if (i < n_items) {
            #pragma unroll
            for (int ni = 0; ni < 2; ni++) {
                int n = ni * 64 + tx * 4;
                float4 v;
                v.x = acc[m][ni * 4 + 0]; v.y = acc[m][ni * 4 + 1];
                v.z = acc[m][ni * 4 + 2]; v.w = acc[m][ni * 4 + 3];
                if (has_bias) {
                    v.x += bias[n + 0]; v.y += bias[n + 1];
                    v.z += bias[n + 2]; v.w += bias[n + 3];
                }
                *(float4*)(O + (size_t)i * HDIM + n) = v;
            }
        }
    }
}

// ---------------------------------------------------------------------------
// head_main_kernel: the dominant GEMM. For block (xi, b, h):
//   A[i][k] = relu(Li[i][k] + ub[b][k])      (fused prologue, K=128)
//   H1      = relu(A @ W1 + b1)              (128x128 tile GEMM, FFMA2)
//   out[b][i] = sigmoid(H1 . W2 + b2)        (fused epilogue reduction)
// A-values are stored duplicated in both f32x2 lanes so the inner loop is
// pure LDS.64 + FFMA2. blockIdx.z picks the head (likes / rated).
// Cycle model: 32 FFMA2 x rt2 = 64 cyc/warp/k-step on fma pipe vs ~24 cyc
// of LDS -> fma-pipe bound; LDS conflicts are non-binding.
// ---------------------------------------------------------------------------
struct HeadArgs {
    int li_off; int ub_off;
    const float *W1, *b1, *W2, *b2;
    float* out;
};

__global__ void __launch_bounds__(256, 2) head_main_kernel(
    HeadArgs h0, HeadArgs h1, int two_heads, int ostride, int n_items)
{
    const HeadArgs& ha = (two_heads && blockIdx.z == 1) ? h1 : h0;
    const float* Li  = g_scratch + ha.li_off;
    const float* ubp = g_scratch + ha.ub_off + blockIdx.y * HDIM;
    const float* __restrict__ W1 = ha.W1;
    const float* __restrict__ b1 = ha.b1;
    const float* __restrict__ W2 = ha.W2;
    const float* __restrict__ b2 = ha.b2;

    __shared__ u64   As2[16][130];     // duplicated A chunk, [k][i]
    __shared__ float Bs[16][132];      // W1 chunk, [k][n] (+pad)
    __shared__ float ub_s[128];
    __shared__ float red[128][17];

    int tid = threadIdx.x, tx = tid & 15, ty = tid >> 4;
    int i0 = blockIdx.x * 128;

    if (tid < 128) ub_s[tid] = ubp[tid];

    u64 acc[8][4];
    #pragma unroll
    for (int m = 0; m < 8; m++)
        #pragma unroll
        for (int p = 0; p < 4; p++) acc[m][p] = 0ull;
    __syncthreads();   // ub_s visible before first A-tile build

    #pragma unroll 1
    for (int kk = 0; kk < 128; kk += 16) {
        // W1 chunk: rows kk..kk+15, fully coalesced float4
        #pragma unroll
        for (int r = 0; r < 2; r++) {
            int q = tid + r * 256;
            int row = q >> 5, c = (q & 31) << 2;
            *(float4*)&Bs[row][c] = *(const float4*)(W1 + (kk + row) * HDIM + c);
        }
        // A chunk: relu(Li + ub), duplicated into both f32x2 lanes
        #pragma unroll
        for (int r = 0; r < 2; r++) {
            int q = tid + r * 256;
            int i = q >> 2, kq = (q & 3) << 2;
            float4 v = make_float4(0.f, 0.f, 0.f, 0.f);
            if (i0 + i < n_items) v = *(const float4*)(Li + (i0 + i) * HDIM + kk + kq);
            As2[kq + 0][i] = dup2(fmaxf(v.x + ub_s[kk + kq + 0], 0.f));
            As2[kq + 1][i] = dup2(fmaxf(v.y + ub_s[kk + kq + 1], 0.f));
            As2[kq + 2][i] = dup2(fmaxf(v.z + ub_s[kk + kq + 2], 0.f));
            As2[kq + 3][i] = dup2(fmaxf(v.w + ub_s[kk + kq + 3], 0.f));
        }
        __syncthreads();

        #pragma unroll
        for (int k = 0; k < 16; k++) {
            u64 ad[8], bp[4];
            #pragma unroll
            for (int mi = 0; mi < 2; mi++)
                #pragma unroll
                for (int j = 0; j < 4; j++)
                    ad[mi * 4 + j] = As2[k][mi * 64 + ty * 4 + j];
            #pragma unroll
            for (int ni = 0; ni < 2; ni++)
                #pragma unroll
                for (int p = 0; p < 2; p++)
                    bp[ni * 2 + p] = *(const u64*)&Bs[k][ni * 64 + tx * 4 + p * 2];
            #pragma unroll
            for (int m = 0; m < 8; m++)
                #pragma unroll
                for (int np = 0; np < 4; np++)
                    acc[m][np] = fma2(ad[m], bp[np], acc[m][np]);
        }
        __syncthreads();
    }

    // Epilogue: h1 = relu(acc + b1); partial = h1 . W2 ; cross-thread reduce
    float b2v = b2[0];
    #pragma unroll
    for (int m = 0; m < 8; m++) {
        int mrow = (m >> 2) * 64 + ty * 4 + (m & 3);
        float partial = 0.f;
        #pragma unroll
        for (int np = 0; np < 4; np++) {
            int n = (np >> 1) * 64 + tx * 4 + (np & 1) * 2;
            float lo, hi; unpack2(acc[m][np], lo, hi);
            float h1a = fmaxf(lo + b1[n],     0.f);
            float h1b = fmaxf(hi + b1[n + 1], 0.f);
            partial += h1a * W2[n] + h1b * W2[n + 1];
        }
        red[mrow][tx] = partial;
    }
    __syncthreads();
    if (tid < 128) {
        float s = 0.f;
        #pragma unroll
        for (int t = 0; t < 16; t++) s += red[tid][t];
        if (i0 + tid < n_items) {
            float val = 1.f / (1.f + expf(-(s + b2v)));
            ha.out[(size_t)blockIdx.y * ostride + i0 + tid] = val;
        }
    }
}

// ---------------------------------------------------------------------------
// Launch
// Input order (metadata): users, user_embedding, item_embedding,
//   likes_{W0,b0,W1,b1,W2,b2}, rated_{...}, pop_{...}
// ---------------------------------------------------------------------------
extern "C" void kernel_launch(void* const* d_in, const int* in_sizes, int n_in,
                              void* d_out, int out_size)
{
    const int*   users = (const int*)d_in[0];
    const float* UE    = (const float*)d_in[1];
    const float* EI    = (const float*)d_in[2];
    const float *lW0 = (const float*)d_in[3],  *lb0 = (const float*)d_in[4];
    const float *lW1 = (const float*)d_in[5],  *lb1 = (const float*)d_in[6];
    const float *lW2 = (const float*)d_in[7],  *lb2 = (const float*)d_in[8];
    const float *rW0 = (const float*)d_in[9],  *rb0 = (const float*)d_in[10];
    const float *rW1 = (const float*)d_in[11], *rb1 = (const float*)d_in[12];
    const float *rW2 = (const float*)d_in[13], *rb2 = (const float*)d_in[14];
    const float *pW0 = (const float*)d_in[15], *pb0 = (const float*)d_in[16];
    const float *pW1 = (const float*)d_in[17], *pb1 = (const float*)d_in[18];
    const float *pW2 = (const float*)d_in[19], *pb2 = (const float*)d_in[20];

    float* out       = (float*)d_out;
    float* likes_out = out;                          // 64*20000
    float* sim_out   = out + BATCH * N_ITEMS;        // 64*64
    float* rated_out = sim_out + BATCH * BATCH;      // 64*20000
    float* pop_out   = rated_out + BATCH * N_ITEMS;  // 20000

    const int NTILES = (N_ITEMS + 127) / 128;        // 157

    user_kernel<<<1, 256>>>(users, UE, lW0, lb0, rW0, rb0, sim_out);

    proj_kernel<<<NTILES, 256>>>(EI, lW0 + DIM * HDIM, nullptr, LI_LIKES, N_ITEMS, 0);
    proj_kernel<<<NTILES, 256>>>(EI, rW0 + DIM * HDIM, nullptr, LI_RATED, N_ITEMS, 0);
    proj_kernel<<<NTILES, 256>>>(EI, pW0,              pb0,     LI_POP,   N_ITEMS, 1);

    HeadArgs hl = { LI_LIKES, UB_OFF,                lW1, lb1, lW2, lb2, likes_out };
    HeadArgs hr = { LI_RATED, UB_OFF + BATCH * HDIM, rW1, rb1, rW2, rb2, rated_out };
    HeadArgs hp = { LI_POP,   ZUB_OFF,               pW1, pb1, pW2, pb2, pop_out   };

    // likes + rated fused into one launch (blockIdx.z = head)
    dim3 g2(NTILES, BATCH, 2);
    head_main_kernel<<<g2, 256>>>(hl, hr, 1, N_ITEMS, N_ITEMS);
    // popular: single "batch" row with zero user bias
    head_main_kernel<<<dim3(NTILES, 1, 1), 256>>>(hp, hp, 0, 0, N_ITEMS);
}

// round 11
// speedup vs baseline: 2.2231x; 2.2231x over previous
#include <cuda_runtime.h>
#include <cuda_bf16.h>

// ---------------------------------------------------------------------------
// Problem: U=100000, I=20000, D=64, H=128, B=64
// out = [likes (64x20000), sim (64x64), rated (64x20000), popular (20000)]
// Head GEMM on mma.sync.m16n8k16 bf16 (base-target HMMA; tcgen05 is
// unavailable: harness PTX targets sm_103, not sm_103a) with hi/lo split
// (3 products) for ~fp32 precision (residual ~u_bf16^2 ~ 1.5e-5).
// ---------------------------------------------------------------------------
#define N_ITEMS 20000
#define DIM     64
#define HDIM    128
#define BATCH   64

#define LI_LIKES 0
#define LI_RATED 2560000            // 20000*128
#define LI_POP   5120000
#define UB_OFF   7680000            // 2 heads * 64 * 128
#define ZUB_OFF  7696384            // 128 zeros (never written -> stays 0)
#define WS_OFF   7696512            // W1 split bf16 images, padded [n][k]
#define WS_HEAD  17408              // floats per head (hi+lo, 128x136 bf16 each)
#define SCRATCH_FLOATS (WS_OFF + 3 * WS_HEAD)

__device__ float g_scratch[SCRATCH_FLOATS];   // zero-initialized at load

typedef unsigned int   u32;
typedef unsigned short u16;

// ---- head-kernel dynamic smem layout (bytes) ----
#define BSTRIDE   272               // bf16 image row stride (136 bf16)
#define IMG_BYTES (128 * BSTRIDE)   // 34816
#define SM_BH  0
#define SM_BL  IMG_BYTES
#define SM_AH  (2 * IMG_BYTES)
#define SM_AL  (3 * IMG_BYTES)
#define SM_LI  (4 * IMG_BYTES)              // fp32 Li tile 128 x LI_PAD
#define LI_PAD 132
#define SM_UB  (SM_LI + 128 * LI_PAD * 4)   // 8 x 128 f32
#define SM_BW  (SM_UB + 8 * 128 * 4)        // b1 (128) + W2 (128)
#define SM_RED (SM_BW + 256 * 4)            // red[128][2]
#define SM_TOTAL (SM_RED + 128 * 2 * 4)     // = 212992 < 227KB

#define LDSM4(r, a) \
    asm volatile("ldmatrix.sync.aligned.m8n8.x4.shared.b16 {%0,%1,%2,%3}, [%4];" \
        : "=r"((r)[0]), "=r"((r)[1]), "=r"((r)[2]), "=r"((r)[3]) : "r"(a))

#define MMA16816(c, a, bb) \
    asm volatile("mma.sync.aligned.m16n8k16.row.col.f32.bf16.bf16.f32 " \
        "{%0,%1,%2,%3}, {%4,%5,%6,%7}, {%8,%9}, {%0,%1,%2,%3};" \
        : "+f"((c)[0]), "+f"((c)[1]), "+f"((c)[2]), "+f"((c)[3]) \
        : "r"((a)[0]), "r"((a)[1]), "r"((a)[2]), "r"((a)[3]), \
          "r"((bb)[0]), "r"((bb)[1]))

// ---------------------------------------------------------------------------
// user_kernel (1 block): eu gather, ub = eu@W0[:64]+b0 for both heads, sim.
// ---------------------------------------------------------------------------
__global__ void __launch_bounds__(256) user_kernel(
    const int* __restrict__ users, const float* __restrict__ UE,
    const float* __restrict__ lW0, const float* __restrict__ lb0,
    const float* __restrict__ rW0, const float* __restrict__ rb0,
    float* __restrict__ sim_out)
{
    __shared__ float eu[64][65];
    __shared__ float Ws[64][64];
    __shared__ float inv[64];
    int tid = threadIdx.x;

    for (int o = tid; o < 4096; o += 256) {
        int b = o >> 6, d = o & 63;
        eu[b][d] = UE[(size_t)users[b] * DIM + d];
    }
    __syncthreads();

    for (int h = 0; h < 2; h++) {
        const float* W0 = h ? rW0 : lW0;
        const float* b0 = h ? rb0 : lb0;
        for (int kh = 0; kh < 2; kh++) {
            for (int o = tid; o < 4096; o += 256) {
                int d = o >> 6, kc = o & 63;
                Ws[d][kc] = W0[d * HDIM + kh * 64 + kc];
            }
            __syncthreads();
            int kc = tid & 63, bg = tid >> 6;
            int k = kh * 64 + kc;
            for (int b = bg; b < 64; b += 4) {
                float acc = b0[k];
                #pragma unroll
                for (int d = 0; d < 64; d++) acc += eu[b][d] * Ws[d][kc];
                g_scratch[UB_OFF + h * (BATCH * HDIM) + b * HDIM + k] = acc;
            }
            __syncthreads();
        }
    }

    if (tid < 64) {
        float ss = 0.f;
        #pragma unroll
        for (int d = 0; d < 64; d++) { float x = eu[tid][d]; ss += x * x; }
        inv[tid] = rsqrtf(fmaxf(ss, 1e-12f));
    }
    __syncthreads();
    for (int o = tid; o < 4096; o += 256) {
        int p = o >> 6, q = o & 63;
        float s = 0.f;
        #pragma unroll
        for (int d = 0; d < 64; d++) s += eu[p][d] * eu[q][d];
        sim_out[o] = -s * inv[p] * inv[q];
    }
}

// ---------------------------------------------------------------------------
// prep_w1_kernel: split W1 into bf16 hi/lo images, [n][k] rows padded to 136.
// ---------------------------------------------------------------------------
__global__ void __launch_bounds__(256) prep_w1_kernel(
    const float* __restrict__ lW1, const float* __restrict__ rW1,
    const float* __restrict__ pW1)
{
    const float* W1 = blockIdx.x == 0 ? lW1 : (blockIdx.x == 1 ? rW1 : pW1);
    u16* img = reinterpret_cast<u16*>(g_scratch + WS_OFF + blockIdx.x * WS_HEAD);
    for (int e = threadIdx.x; e < HDIM * HDIM; e += 256) {
        int n = e >> 7, k = e & 127;
        float w = W1[k * HDIM + n];
        __nv_bfloat16 hi = __float2bfloat16(w);
        __nv_bfloat16 lo = __float2bfloat16(w - __bfloat162float(hi));
        img[n * 136 + k]         = __bfloat16_as_ushort(hi);
        img[17408 + n * 136 + k] = __bfloat16_as_ushort(lo);
    }
}

// ---------------------------------------------------------------------------
// proj3_kernel: three item projections in one launch (blockIdx.y = which).
// ---------------------------------------------------------------------------
struct ProjArg { const float* W; const float* bias; int o_off; int has_bias; };

__global__ void __launch_bounds__(256) proj3_kernel(
    const float* __restrict__ E, ProjArg p0, ProjArg p1, ProjArg p2, int n_items)
{
    const ProjArg& pa = blockIdx.y == 0 ? p0 : (blockIdx.y == 1 ? p1 : p2);
    const float* __restrict__ W = pa.W;
    const float* __restrict__ bias = pa.bias;
    float* O = g_scratch + pa.o_off;
    __shared__ float Es[16][132];
    __shared__ float Ws[16][132];
    int tid = threadIdx.x, tx = tid & 15, ty = tid >> 4;
    int i0 = blockIdx.x * 128;

    float acc[8][8];
    #pragma unroll
    for (int m = 0; m < 8; m++)
        #pragma unroll
        for (int n = 0; n < 8; n++) acc[m][n] = 0.f;

    #pragma unroll 1
    for (int kk = 0; kk < 64; kk += 16) {
        #pragma unroll
        for (int r = 0; r < 2; r++) {
            int q = tid + r * 256;
            int row = q >> 5, c = (q & 31) << 2;
            *(float4*)&Ws[row][c] = *(const float4*)(W + (kk + row) * HDIM + c);
        }
        #pragma unroll
        for (int r = 0; r < 2; r++) {
            int q = tid + r * 256;
            int i = q >> 2, kq = (q & 3) << 2;
            float4 v = make_float4(0.f, 0.f, 0.f, 0.f);
            if (i0 + i < n_items) v = *(const float4*)(E + (i0 + i) * DIM + kk + kq);
            Es[kq + 0][i] = v.x; Es[kq + 1][i] = v.y;
            Es[kq + 2][i] = v.z; Es[kq + 3][i] = v.w;
        }
        __syncthreads();
        #pragma unroll
        for (int k = 0; k < 16; k++) {
            float a[8], bb[8];
            #pragma unroll
            for (int mi = 0; mi < 2; mi++)
                #pragma unroll
                for (int j = 0; j < 4; j++) a[mi * 4 + j] = Es[k][mi * 64 + ty * 4 + j];
            #pragma unroll
            for (int ni = 0; ni < 2; ni++)
                #pragma unroll
                for (int j = 0; j < 4; j++) bb[ni * 4 + j] = Ws[k][ni * 64 + tx * 4 + j];
            #pragma unroll
            for (int m = 0; m < 8; m++)
                #pragma unroll
                for (int n = 0; n < 8; n++) acc[m][n] += a[m] * bb[n];
        }
        __syncthreads();
    }

    #pragma unroll
    for (int m = 0; m < 8; m++) {
        int i = i0 + (m >> 2) * 64 + ty * 4 + (m & 3);
        if (i < n_items) {
            #pragma unroll
            for (int ni = 0; ni < 2; ni++) {
                int n = ni * 64 + tx * 4;
                float4 v;
                v.x = acc[m][ni * 4 + 0]; v.y = acc[m][ni * 4 + 1];
                v.z = acc[m][ni * 4 + 2]; v.w = acc[m][ni * 4 + 3];
                if (pa.has_bias) {
                    v.x += bias[n + 0]; v.y += bias[n + 1];
                    v.z += bias[n + 2]; v.w += bias[n + 3];
                }
                *(float4*)(O + (size_t)i * HDIM + n) = v;
            }
        }
    }
}

// ---------------------------------------------------------------------------
// head_mma_kernel: per block (item-tile, batch-group of nb, head):
//   stage B hi/lo + Li fp32 tile once; per batch: A = relu(Li+ub) split to
//   bf16 hi/lo; D = Ah@Bh + Al@Bh + Ah@Bl via mma.sync m16n8k16;
//   out = sigmoid(relu(D + b1).W2 + b2).
// Warps: 4x2 (M x N); warp tile 32x64; per kt: 4 A-ldsm + 8 B-ldsm, 48 mma.
// ---------------------------------------------------------------------------
struct HeadTC {
    int li_off, ub_off, ws_off;
    const float *b1, *W2, *b2;
    float* out;
};

__global__ void __launch_bounds__(256, 1)
head_mma_kernel(HeadTC h0, HeadTC h1, int two_heads, int nb, int ostride, int n_items)
{
    extern __shared__ char smem[];
    const HeadTC& ha = (two_heads && blockIdx.z == 1) ? h1 : h0;
    int tid = threadIdx.x, lane = tid & 31, wid = tid >> 5;
    int wm = wid & 3, wn = wid >> 2;
    int i0 = blockIdx.x * 128;
    int bg = blockIdx.y;

    // Stage B hi/lo images (69632B, exact 17 uint4 per thread).
    {
        const uint4* src = (const uint4*)(g_scratch + ha.ws_off);
        uint4* dst = (uint4*)(smem + SM_BH);
        #pragma unroll
        for (int r = 0; r < 17; r++) dst[tid + r * 256] = src[tid + r * 256];
    }
    // Stage Li tile fp32 (zero-fill invalid rows).
    {
        float* li = (float*)(smem + SM_LI);
        const float* g = g_scratch + ha.li_off;
        #pragma unroll
        for (int it = 0; it < 16; it++) {
            int idx = tid + it * 256;
            int row = idx >> 5, c4 = (idx & 31) << 2;
            float4 v = make_float4(0.f, 0.f, 0.f, 0.f);
            if (i0 + row < n_items) v = *(const float4*)(g + (size_t)(i0 + row) * HDIM + c4);
            *(float4*)(li + row * LI_PAD + c4) = v;
        }
    }
    // ub rows for this batch group; b1/W2.
    {
        float* ub = (float*)(smem + SM_UB);
        for (int idx = tid; idx < nb * 128; idx += 256)
            ub[idx] = g_scratch[ha.ub_off + (size_t)(bg * nb + (idx >> 7)) * HDIM + (idx & 127)];
        float* bw = (float*)(smem + SM_BW);
        if (tid < 128) bw[tid] = ha.b1[tid];
        else bw[tid] = ha.W2[tid - 128];
    }
    __syncthreads();

    const float* li_sm = (const float*)(smem + SM_LI);
    const float* ub_sm = (const float*)(smem + SM_UB);
    const float* b1_sm = (const float*)(smem + SM_BW);
    const float* w2_sm = (const float*)(smem + SM_BW) + 128;
    float* red = (float*)(smem + SM_RED);
    float b2v = ha.b2[0];

    u32 sb;
    asm("{ .reg .u64 t; cvta.to.shared.u64 t, %1; cvt.u32.u64 %0, t; }" : "=r"(sb) : "l"(smem));
    // ldmatrix lane pointer offsets (canonical x4 maps)
    int arow  = ((lane >> 3) & 1) * 8 + (lane & 7);
    int acolh = lane >> 4;                 // k-half
    int brow  = (lane >> 4) * 8 + (lane & 7);
    int bcolh = (lane >> 3) & 1;
    u32 aoff = (u32)((wm * 32 + arow) * BSTRIDE + acolh * 16);
    u32 boff = (u32)((wn * 64 + brow) * BSTRIDE + bcolh * 16);

    #pragma unroll 1
    for (int b = 0; b < nb; b++) {
        // Build A hi/lo from relu(Li + ub[b]).
        {
            int r = tid & 127, ch = tid >> 7;
            const float* lrow = li_sm + r * LI_PAD + ch * 64;
            const float* urow = ub_sm + b * 128 + ch * 64;
            char* ahp = smem + SM_AH + r * BSTRIDE + ch * 128;
            char* alp = smem + SM_AL + r * BSTRIDE + ch * 128;
            #pragma unroll
            for (int j = 0; j < 16; j++) {
                float4 v = *(const float4*)(lrow + 4 * j);
                float a0 = fmaxf(v.x + urow[4 * j + 0], 0.f);
                float a1 = fmaxf(v.y + urow[4 * j + 1], 0.f);
                float a2 = fmaxf(v.z + urow[4 * j + 2], 0.f);
                float a3 = fmaxf(v.w + urow[4 * j + 3], 0.f);
                __nv_bfloat16 h0b = __float2bfloat16(a0), h1b = __float2bfloat16(a1);
                __nv_bfloat16 h2b = __float2bfloat16(a2), h3b = __float2bfloat16(a3);
                u32 hi01 = (u32)__bfloat16_as_ushort(h0b) | ((u32)__bfloat16_as_ushort(h1b) << 16);
                u32 hi23 = (u32)__bfloat16_as_ushort(h2b) | ((u32)__bfloat16_as_ushort(h3b) << 16);
                __nv_bfloat16 l0b = __float2bfloat16(a0 - __bfloat162float(h0b));
                __nv_bfloat16 l1b = __float2bfloat16(a1 - __bfloat162float(h1b));
                __nv_bfloat16 l2b = __float2bfloat16(a2 - __bfloat162float(h2b));
                __nv_bfloat16 l3b = __float2bfloat16(a3 - __bfloat162float(h3b));
                u32 lo01 = (u32)__bfloat16_as_ushort(l0b) | ((u32)__bfloat16_as_ushort(l1b) << 16);
                u32 lo23 = (u32)__bfloat16_as_ushort(l2b) | ((u32)__bfloat16_as_ushort(l3b) << 16);
                *(u32*)(ahp + 8 * j)     = hi01;
                *(u32*)(ahp + 8 * j + 4) = hi23;
                *(u32*)(alp + 8 * j)     = lo01;
                *(u32*)(alp + 8 * j + 4) = lo23;
            }
        }
        __syncthreads();

        float acc[2][8][4];
        #pragma unroll
        for (int mt = 0; mt < 2; mt++)
            #pragma unroll
            for (int nt = 0; nt < 8; nt++)
                #pragma unroll
                for (int q = 0; q < 4; q++) acc[mt][nt][q] = 0.f;

        #pragma unroll
        for (int kt = 0; kt < 8; kt++) {
            u32 ah[2][4], al[2][4], bh[8][2], bl[8][2];
            #pragma unroll
            for (int mt = 0; mt < 2; mt++) {
                LDSM4(ah[mt], sb + SM_AH + aoff + (u32)(mt * 16 * BSTRIDE + kt * 32));
                LDSM4(al[mt], sb + SM_AL + aoff + (u32)(mt * 16 * BSTRIDE + kt * 32));
            }
            #pragma unroll
            for (int p = 0; p < 4; p++) {
                u32 t4[4];
                LDSM4(t4, sb + SM_BH + boff + (u32)(p * 16 * BSTRIDE + kt * 32));
                bh[2 * p][0] = t4[0]; bh[2 * p][1] = t4[1];
                bh[2 * p + 1][0] = t4[2]; bh[2 * p + 1][1] = t4[3];
                LDSM4(t4, sb + SM_BL + boff + (u32)(p * 16 * BSTRIDE + kt * 32));
                bl[2 * p][0] = t4[0]; bl[2 * p][1] = t4[1];
                bl[2 * p + 1][0] = t4[2]; bl[2 * p + 1][1] = t4[3];
            }
            #pragma unroll
            for (int mt = 0; mt < 2; mt++)
                #pragma unroll
                for (int nt = 0; nt < 8; nt++) {
                    MMA16816(acc[mt][nt], ah[mt], bh[nt]);
                    MMA16816(acc[mt][nt], al[mt], bh[nt]);
                    MMA16816(acc[mt][nt], ah[mt], bl[nt]);
                }
        }

        // Epilogue: relu(+b1) . W2, quad-shfl reduce, cross-warp combine.
        #pragma unroll
        for (int mt = 0; mt < 2; mt++) {
            #pragma unroll
            for (int rh = 0; rh < 2; rh++) {
                float part = 0.f;
                #pragma unroll
                for (int nt = 0; nt < 8; nt++) {
                    int col = wn * 64 + nt * 8 + (lane & 3) * 2;
                    part += fmaxf(acc[mt][nt][rh * 2 + 0] + b1_sm[col], 0.f) * w2_sm[col];
                    part += fmaxf(acc[mt][nt][rh * 2 + 1] + b1_sm[col + 1], 0.f) * w2_sm[col + 1];
                }
                part += __shfl_xor_sync(0xffffffffu, part, 1);
                part += __shfl_xor_sync(0xffffffffu, part, 2);
                if ((lane & 3) == 0) {
                    int row = wm * 32 + mt * 16 + rh * 8 + (lane >> 2);
                    red[row * 2 + wn] = part;
                }
            }
        }
        __syncthreads();
        if (tid < 128 && i0 + tid < n_items) {
            float s = red[tid * 2] + red[tid * 2 + 1] + b2v;
            ha.out[(size_t)(bg * nb + b) * ostride + i0 + tid] = 1.f / (1.f + expf(-s));
        }
        __syncthreads();
    }
}

// ---------------------------------------------------------------------------
// Launch. Inputs: users, user_embedding, item_embedding,
//   likes_{W0,b0,W1,b1,W2,b2}, rated_{...}, pop_{...}
// ---------------------------------------------------------------------------
extern "C" void kernel_launch(void* const* d_in, const int* in_sizes, int n_in,
                              void* d_out, int out_size)
{
    const int*   users = (const int*)d_in[0];
    const float* UE    = (const float*)d_in[1];
    const float* EI    = (const float*)d_in[2];
    const float *lW0 = (const float*)d_in[3],  *lb0 = (const float*)d_in[4];
    const float *lW1 = (const float*)d_in[5],  *lb1 = (const float*)d_in[6];
    const float *lW2 = (const float*)d_in[7],  *lb2 = (const float*)d_in[8];
    const float *rW0 = (const float*)d_in[9],  *rb0 = (const float*)d_in[10];
    const float *rW1 = (const float*)d_in[11], *rb1 = (const float*)d_in[12];
    const float *rW2 = (const float*)d_in[13], *rb2 = (const float*)d_in[14];
    const float *pW0 = (const float*)d_in[15], *pb0 = (const float*)d_in[16];
    const float *pW1 = (const float*)d_in[17], *pb1 = (const float*)d_in[18];
    const float *pW2 = (const float*)d_in[19], *pb2 = (const float*)d_in[20];

    float* out       = (float*)d_out;
    float* likes_out = out;
    float* sim_out   = out + BATCH * N_ITEMS;
    float* rated_out = sim_out + BATCH * BATCH;
    float* pop_out   = rated_out + BATCH * N_ITEMS;

    const int NTILES = (N_ITEMS + 127) / 128;   // 157

    cudaFuncSetAttribute(head_mma_kernel,
                         cudaFuncAttributeMaxDynamicSharedMemorySize, SM_TOTAL);

    user_kernel<<<1, 256>>>(users, UE, lW0, lb0, rW0, rb0, sim_out);
    prep_w1_kernel<<<3, 256>>>(lW1, rW1, pW1);

    ProjArg pl = { lW0 + DIM * HDIM, nullptr, LI_LIKES, 0 };
    ProjArg pr = { rW0 + DIM * HDIM, nullptr, LI_RATED, 0 };
    ProjArg pp = { pW0,              pb0,     LI_POP,   1 };
    proj3_kernel<<<dim3(NTILES, 3), 256>>>(EI, pl, pr, pp, N_ITEMS);

    HeadTC hl = { LI_LIKES, UB_OFF,                WS_OFF,               lb1, lW2, lb2, likes_out };
    HeadTC hr = { LI_RATED, UB_OFF + BATCH * HDIM, WS_OFF + WS_HEAD,     rb1, rW2, rb2, rated_out };
    HeadTC hp = { LI_POP,   ZUB_OFF,               WS_OFF + 2 * WS_HEAD, pb1, pW2, pb2, pop_out   };

    // likes + rated: 8 batches per block, fused heads on blockIdx.z
    head_mma_kernel<<<dim3(NTILES, 8, 2), 256, SM_TOTAL>>>(hl, hr, 1, 8, N_ITEMS, N_ITEMS);
    // popular: one pseudo-batch with zero user bias
    head_mma_kernel<<<dim3(NTILES, 1, 1), 256, SM_TOTAL>>>(hp, hp, 0, 1, 0, N_ITEMS);
}